// round 6
// baseline (speedup 1.0000x reference)
#include <cuda_runtime.h>
#include <cstdint>

#define N_ACT   1500000
#define ROWS_PB 128                                 // 4 warps x 32 rows
#define NB_CONV ((N_ACT + ROWS_PB - 1) / ROWS_PB)   // 11719 blocks
#define NB_ELT  ((N_ACT * 8) / 256)                 // N*32 floats / 4 per thread / 256
#define BN_EPS  1e-5f
#define XS      36                                  // smem stride (floats) per cin

// ---------------- scratch (no allocations allowed) ----------------
__device__ float g_h1[(size_t)N_ACT * 32];     // conv1 raw output
__device__ float g_h2[(size_t)N_ACT * 32];     // conv2 raw output
__device__ float g_part1[64 * NB_CONV];        // transposed: [stat][block]
__device__ float g_part2[64 * NB_CONV];
__device__ float g_stat1[64];                  // summed stats [sum(32), sumsq(32)]
__device__ float g_stat2[64];
__device__ float g_coef1[64];                  // [a(32), c(32)] : y = a*h + c
__device__ float g_coef2[64];

// ---------------- f32x2 helpers (Blackwell packed fp32) ----------------
__device__ __forceinline__ unsigned long long splat2(float w) {
    unsigned long long r;
    asm("mov.b64 %0, {%1, %1};" : "=l"(r) : "f"(w));
    return r;
}
__device__ __forceinline__ unsigned long long pack2(float lo, float hi) {
    unsigned long long r;
    asm("mov.b64 %0, {%1, %2};" : "=l"(r) : "f"(lo), "f"(hi));
    return r;
}
__device__ __forceinline__ float2 unpack2(unsigned long long v) {
    float2 f;
    asm("mov.b64 {%0, %1}, %2;" : "=f"(f.x), "=f"(f.y) : "l"(v));
    return f;
}
__device__ __forceinline__ void fma2(unsigned long long& acc,
                                     unsigned long long x,
                                     unsigned long long w) {
    asm("fma.rn.f32x2 %0, %1, %2, %0;" : "+l"(acc) : "l"(x), "l"(w));
}

// ---------------- conv: H[i] = sum_k gather(X, idx[k]) @ W[k] ----------------
// Warp tile: 32 rows x 32 cout. lane = rg*4+cg; lane computes 4 rows x 8 couts.
// Gather (lane = cin) pipelined one k ahead into a double-buffered smem tile.
template<int WHICH>
__global__ __launch_bounds__(128, 4) void conv_kernel(
    const float* __restrict__ Xin, const int* __restrict__ IDX,
    const float* __restrict__ Wg)
{
    const float* X    = WHICH ? g_h1    : Xin;
    float*       H    = WHICH ? g_h2    : g_h1;
    float*       part = WHICH ? g_part2 : g_part1;

    // double-buffered per-warp transposed tile: [cin][row], stride XS floats
    __shared__ __align__(16) float sX[2][4][32 * XS];
    __shared__ float red[2][4][32];

    const int tid   = threadIdx.x;
    const int warp  = tid >> 5;
    const int lane  = tid & 31;
    const int rg    = lane >> 2;            // row group: rows [rg*4, rg*4+4)
    const int cg    = lane & 3;             // cout group: couts [cg*8, cg*8+8)
    const int wbase = blockIdx.x * ROWS_PB + warp * 32;

    float* xw0 = sX[0][warp];
    float* xw1 = sX[1][warp];

    // bn1+relu coefs for the fused gather transform (lane == channel)
    float a_bn = 0.f, c_bn = 0.f;
    if (WHICH) { a_bn = g_coef1[lane]; c_bn = g_coef1[32 + lane]; }

    unsigned long long acc[16];             // acc[r*4+p]: row r, cout pair p
#pragma unroll
    for (int i = 0; i < 16; i++) acc[i] = 0ULL;

    // idx row for this lane; clamp keeps tail legal
    const int rowc = min(wbase + lane, N_ACT - 1);

    float vals[16];

#define GATHER_HALF(MYJ, BASE)                                            \
    {                                                                     \
        _Pragma("unroll")                                                 \
        for (int r = 0; r < 16; r++) {                                    \
            int j = __shfl_sync(0xffffffffu, (MYJ), (BASE) + r);          \
            float t = 0.f;                                                \
            if (j < N_ACT) {                                              \
                t = X[(size_t)j * 32 + lane];                             \
                if (WHICH) t = fmaxf(fmaf(t, a_bn, c_bn), 0.f);           \
            }                                                             \
            vals[r] = t;                                                  \
        }                                                                 \
    }
#define STORE_HALF(DST, BASE)                                             \
    {                                                                     \
        _Pragma("unroll")                                                 \
        for (int q = 0; q < 4; q++)                                       \
            *(float4*)((DST) + lane * XS + (BASE) + 4 * q) =              \
                make_float4(vals[4*q], vals[4*q+1], vals[4*q+2], vals[4*q+3]); \
    }
#define COMPUTE_HALF(SRC, WK, CBASE)                                      \
    {                                                                     \
        _Pragma("unroll")                                                 \
        for (int ci = 0; ci < 16; ci++) {                                 \
            const int c = (CBASE) + ci;                                   \
            float4 xv = *(const float4*)((SRC) + c * XS + (rg << 2));     \
            float4 wa = *(const float4*)((WK) + c * 32 + (cg << 3));      \
            float4 wb = *(const float4*)((WK) + c * 32 + (cg << 3) + 4);  \
            unsigned long long wp0 = pack2(wa.x, wa.y);                   \
            unsigned long long wp1 = pack2(wa.z, wa.w);                   \
            unsigned long long wp2 = pack2(wb.x, wb.y);                   \
            unsigned long long wp3 = pack2(wb.z, wb.w);                   \
            unsigned long long xs;                                        \
            xs = splat2(xv.x);                                            \
            fma2(acc[0], xs, wp0); fma2(acc[1], xs, wp1);                 \
            fma2(acc[2], xs, wp2); fma2(acc[3], xs, wp3);                 \
            xs = splat2(xv.y);                                            \
            fma2(acc[4], xs, wp0); fma2(acc[5], xs, wp1);                 \
            fma2(acc[6], xs, wp2); fma2(acc[7], xs, wp3);                 \
            xs = splat2(xv.z);                                            \
            fma2(acc[8],  xs, wp0); fma2(acc[9],  xs, wp1);               \
            fma2(acc[10], xs, wp2); fma2(acc[11], xs, wp3);               \
            xs = splat2(xv.w);                                            \
            fma2(acc[12], xs, wp0); fma2(acc[13], xs, wp1);               \
            fma2(acc[14], xs, wp2); fma2(acc[15], xs, wp3);               \
        }                                                                 \
    }

    // ---- prologue: gather k=0 into buf0 (full latency exposed once) ----
    int myj_cur = IDX[rowc];                       // idx for k=0
    GATHER_HALF(myj_cur, 0);  STORE_HALF(xw0, 0);
    GATHER_HALF(myj_cur, 16); STORE_HALF(xw0, 16);
    int myj_nxt = IDX[(size_t)N_ACT + rowc];       // idx for k=1

#pragma unroll 1
    for (int k = 0; k < 8; k++) {
        __syncwarp();                              // buf[k&1] complete
        const float* xw = (k & 1) ? xw1 : xw0;
        float*       xn = (k & 1) ? xw0 : xw1;
        const float* wk = Wg + k * 1024;
        const int    myj = myj_nxt;                // idx for k+1

        // phase A: launch gather LDGs (rows 0..15 of k+1), compute cin 0..15
        if (k < 7) GATHER_HALF(myj, 0);
        COMPUTE_HALF(xw, wk, 0);
        if (k < 7) STORE_HALF(xn, 0);

        // phase B: gather rows 16..31 of k+1, compute cin 16..31
        if (k < 7) GATHER_HALF(myj, 16);
        if (k < 6) myj_nxt = IDX[(size_t)(k + 2) * N_ACT + rowc];
        COMPUTE_HALF(xw, wk, 16);
        if (k < 7) STORE_HALF(xn, 16);
    }

    // ---- epilogue: stats + store. lane owns rows rg*4..+3, couts cg*8..+7 ----
    const int rbase = wbase + (rg << 2);
    float s[8], sq[8];
#pragma unroll
    for (int j = 0; j < 8; j++) { s[j] = 0.f; sq[j] = 0.f; }
#pragma unroll
    for (int r = 0; r < 4; r++) {
        if (rbase + r < N_ACT) {
#pragma unroll
            for (int p = 0; p < 4; p++) {
                float2 f = unpack2(acc[r * 4 + p]);
                s [2*p]   += f.x;  sq[2*p]   += f.x * f.x;
                s [2*p+1] += f.y;  sq[2*p+1] += f.y * f.y;
            }
        }
    }
    // reduce over the 8 row-groups (lane xor 4,8,16 varies rg only)
#pragma unroll
    for (int off = 4; off <= 16; off <<= 1) {
#pragma unroll
        for (int j = 0; j < 8; j++) {
            s [j] += __shfl_xor_sync(0xffffffffu, s [j], off);
            sq[j] += __shfl_xor_sync(0xffffffffu, sq[j], off);
        }
    }
    if (rg == 0) {
#pragma unroll
        for (int j = 0; j < 8; j++) {
            red[0][warp][cg * 8 + j] = s[j];
            red[1][warp][cg * 8 + j] = sq[j];
        }
    }

    // store H: per row, 8 contiguous floats -> 2x STG.128
#pragma unroll
    for (int r = 0; r < 4; r++) {
        int r0 = rbase + r;
        if (r0 < N_ACT) {
            float2 f0 = unpack2(acc[r*4+0]), f1 = unpack2(acc[r*4+1]);
            float2 f2 = unpack2(acc[r*4+2]), f3 = unpack2(acc[r*4+3]);
            float* hp = H + (size_t)r0 * 32 + (cg << 3);
            *(float4*)(hp)     = make_float4(f0.x, f0.y, f1.x, f1.y);
            *(float4*)(hp + 4) = make_float4(f2.x, f2.y, f3.x, f3.y);
        }
    }

    __syncthreads();
    if (warp == 0) {
        float ts = 0.f, tq = 0.f;
#pragma unroll
        for (int w = 0; w < 4; w++) { ts += red[0][w][lane]; tq += red[1][w][lane]; }
        part[(size_t)lane        * NB_CONV + blockIdx.x] = ts;
        part[(size_t)(32 + lane) * NB_CONV + blockIdx.x] = tq;
    }
#undef GATHER_HALF
#undef STORE_HALF
#undef COMPUTE_HALF
}

// ---------------- reduce: 64 blocks, block c sums its stat row (coalesced) ----
__global__ void reduce_kernel(int which)
{
    const float* part = which ? g_part2 : g_part1;
    float*       stat = which ? g_stat2 : g_stat1;

    const float* row = part + (size_t)blockIdx.x * NB_CONV;
    float s = 0.f;
#pragma unroll 4
    for (int i = threadIdx.x; i < NB_CONV; i += 256) s += row[i];

    __shared__ float sh[256];
    sh[threadIdx.x] = s;
    __syncthreads();
#pragma unroll
    for (int o = 128; o > 0; o >>= 1) {
        if (threadIdx.x < o) sh[threadIdx.x] += sh[threadIdx.x + o];
        __syncthreads();
    }
    if (threadIdx.x == 0) stat[blockIdx.x] = sh[0];
}

// ---------------- coefs: a = g*rsqrt(var+eps), c = b - mean*a ----------------
__global__ void coef_kernel(const float* __restrict__ gamma,
                            const float* __restrict__ beta, int which)
{
    const float* stat = which ? g_stat2 : g_stat1;
    float*       coef = which ? g_coef2 : g_coef1;
    int c = threadIdx.x;   // 32 threads
    float mean = stat[c] / (float)N_ACT;
    float var  = fmaxf(stat[32 + c] / (float)N_ACT - mean * mean, 0.f);
    float a    = gamma[c] * rsqrtf(var + BN_EPS);
    coef[c]      = a;
    coef[32 + c] = beta[c] - mean * a;
}

// ---------------- bn2 + residual add -> out ----------------
__global__ void final_kernel(const float* __restrict__ X, float* __restrict__ O)
{
    int i4 = blockIdx.x * 256 + threadIdx.x;
    int cb = i4 & 7;
    float4 a = ((const float4*)g_coef2)[cb];
    float4 c = ((const float4*)g_coef2)[8 + cb];
    float4 v = ((const float4*)g_h2)[i4];
    float4 x = ((const float4*)X)[i4];
    float4 o;
    o.x = fmaf(v.x, a.x, c.x) + x.x;
    o.y = fmaf(v.y, a.y, c.y) + x.y;
    o.z = fmaf(v.z, a.z, c.z) + x.z;
    o.w = fmaf(v.w, a.w, c.w) + x.w;
    ((float4*)O)[i4] = o;
}

extern "C" void kernel_launch(void* const* d_in, const int* in_sizes, int n_in,
                              void* d_out, int out_size)
{
    const float* x   = (const float*)d_in[0];
    const int*   idx = (const int*)  d_in[1];
    const float* W1  = (const float*)d_in[2];
    const float* g1  = (const float*)d_in[3];
    const float* b1  = (const float*)d_in[4];
    const float* W2  = (const float*)d_in[5];
    const float* g2  = (const float*)d_in[6];
    const float* b2  = (const float*)d_in[7];
    float* out = (float*)d_out;

    conv_kernel<0><<<NB_CONV, 128>>>(x, idx, W1);   // h1 = conv1(x), partials1
    reduce_kernel <<<64, 256>>>(0);                 // stat1
    coef_kernel   <<<1, 32>>>(g1, b1, 0);           // coef1
    conv_kernel<1><<<NB_CONV, 128>>>(x, idx, W2);   // h2 = conv2(bn1relu(h1)), partials2
    reduce_kernel <<<64, 256>>>(1);                 // stat2
    coef_kernel   <<<1, 32>>>(g2, b2, 1);           // coef2
    final_kernel  <<<NB_ELT, 256>>>(x, out);        // out = bn2(h2) + x
}

// round 7
// speedup vs baseline: 1.1937x; 1.1937x over previous
#include <cuda_runtime.h>
#include <cstdint>

#define N_ACT   1500000
#define ROWS_PB 128                                 // 8 warps x 16 rows
#define NB_CONV ((N_ACT + ROWS_PB - 1) / ROWS_PB)   // 11719 blocks
#define NB_ELT  ((N_ACT * 8) / 256)                 // N*32 floats / 4 per thread / 256
#define BN_EPS  1e-5f
#define XS      20                                  // smem stride (floats) per cin

// ---------------- scratch (no allocations allowed) ----------------
__device__ float g_h1[(size_t)N_ACT * 32];     // conv1 raw output
__device__ float g_h2[(size_t)N_ACT * 32];     // conv2 raw output
__device__ float g_part1[64 * NB_CONV];        // transposed: [stat][block]
__device__ float g_part2[64 * NB_CONV];
__device__ float g_stat1[64];                  // summed stats [sum(32), sumsq(32)]
__device__ float g_stat2[64];
__device__ float g_coef1[64];                  // [a(32), c(32)] : y = a*h + c
__device__ float g_coef2[64];

// ---------------- f32x2 helpers (Blackwell packed fp32) ----------------
__device__ __forceinline__ unsigned long long splat2(float w) {
    unsigned long long r;
    asm("mov.b64 %0, {%1, %1};" : "=l"(r) : "f"(w));
    return r;
}
__device__ __forceinline__ unsigned long long pack2(float lo, float hi) {
    unsigned long long r;
    asm("mov.b64 %0, {%1, %2};" : "=l"(r) : "f"(lo), "f"(hi));
    return r;
}
__device__ __forceinline__ float2 unpack2(unsigned long long v) {
    float2 f;
    asm("mov.b64 {%0, %1}, %2;" : "=f"(f.x), "=f"(f.y) : "l"(v));
    return f;
}
__device__ __forceinline__ void fma2(unsigned long long& acc,
                                     unsigned long long x,
                                     unsigned long long w) {
    asm("fma.rn.f32x2 %0, %1, %2, %0;" : "+l"(acc) : "l"(x), "l"(w));
}

// ---------------- conv: H[i] = sum_k gather(X, idx[k]) @ W[k] ----------------
// Warp tile: 16 rows x 32 cout. lane = rg*8+cg: rg = 4-row group, cg = 4-cout group.
// acc[r*2+p] (f32x2): row rbase+r, couts cg*4+2p, cg*4+2p+1.
// Gather (lane = cin) pipelined one k ahead into a double-buffered smem tile.
template<int WHICH>
__global__ __launch_bounds__(256, 4) void conv_kernel(
    const float* __restrict__ Xin, const int* __restrict__ IDX,
    const float* __restrict__ Wg)
{
    const float* X    = WHICH ? g_h1    : Xin;
    float*       H    = WHICH ? g_h2    : g_h1;
    float*       part = WHICH ? g_part2 : g_part1;

    // double-buffered per-warp transposed tile: [cin][row], stride XS floats
    __shared__ __align__(16) float sX[2][8][32 * XS];   // 40960 B
    __shared__ float red[2][8][32];                     //  2048 B

    const int tid   = threadIdx.x;
    const int warp  = tid >> 5;
    const int lane  = tid & 31;
    const int rg    = lane >> 3;            // rows [rg*4, rg*4+4)
    const int cg    = lane & 7;             // couts [cg*4, cg*4+4)
    const int wbase = blockIdx.x * ROWS_PB + warp * 16;

    float* xw0 = sX[0][warp];
    float* xw1 = sX[1][warp];

    // bn1+relu coefs for the fused gather transform (lane == channel)
    float a_bn = 0.f, c_bn = 0.f;
    if (WHICH) { a_bn = g_coef1[lane]; c_bn = g_coef1[32 + lane]; }

    unsigned long long acc[8];
#pragma unroll
    for (int i = 0; i < 8; i++) acc[i] = 0ULL;

    // idx row for this lane (lanes 16-31 duplicate 0-15); clamp keeps tail legal
    const int rowc = min(wbase + (lane & 15), N_ACT - 1);

    float vals[8];

#define GATHER8(MYJ, RB)                                                  \
    {                                                                     \
        _Pragma("unroll")                                                 \
        for (int r = 0; r < 8; r++) {                                     \
            int j = __shfl_sync(0xffffffffu, (MYJ), (RB) + r);            \
            float t = 0.f;                                                \
            if (j < N_ACT) {                                              \
                t = X[(size_t)j * 32 + lane];                             \
                if (WHICH) t = fmaxf(fmaf(t, a_bn, c_bn), 0.f);           \
            }                                                             \
            vals[r] = t;                                                  \
        }                                                                 \
    }
#define STORE8(DST, RB)                                                   \
    {                                                                     \
        *(float4*)((DST) + lane * XS + (RB))     =                        \
            make_float4(vals[0], vals[1], vals[2], vals[3]);              \
        *(float4*)((DST) + lane * XS + (RB) + 4) =                        \
            make_float4(vals[4], vals[5], vals[6], vals[7]);              \
    }
#define COMPUTE16(SRC, WK, CB)                                            \
    {                                                                     \
        _Pragma("unroll")                                                 \
        for (int ci = 0; ci < 16; ci++) {                                 \
            const int c = (CB) + ci;                                      \
            float4 xv = *(const float4*)((SRC) + c * XS + (rg << 2));     \
            float4 wv = *(const float4*)((WK) + c * 32 + (cg << 2));      \
            unsigned long long wp0 = pack2(wv.x, wv.y);                   \
            unsigned long long wp1 = pack2(wv.z, wv.w);                   \
            unsigned long long xs;                                        \
            xs = splat2(xv.x); fma2(acc[0], xs, wp0); fma2(acc[1], xs, wp1); \
            xs = splat2(xv.y); fma2(acc[2], xs, wp0); fma2(acc[3], xs, wp1); \
            xs = splat2(xv.z); fma2(acc[4], xs, wp0); fma2(acc[5], xs, wp1); \
            xs = splat2(xv.w); fma2(acc[6], xs, wp0); fma2(acc[7], xs, wp1); \
        }                                                                 \
    }

    // ---- prologue: gather k=0 into buf0 (full latency exposed once) ----
    int myj_cur = IDX[rowc];                       // idx for k=0
    GATHER8(myj_cur, 0); STORE8(xw0, 0);
    GATHER8(myj_cur, 8); STORE8(xw0, 8);
    int myj_nxt = IDX[(size_t)N_ACT + rowc];       // idx for k=1

#pragma unroll 1
    for (int k = 0; k < 8; k++) {
        __syncwarp();                              // buf[k&1] fully written
        const float* xw = (k & 1) ? xw1 : xw0;
        float*       xn = (k & 1) ? xw0 : xw1;
        const float* wk = Wg + k * 1024;
        const int    myj = myj_nxt;                // idx for k+1 (ready)

        // phase A: launch gather LDGs rows 0..7 of k+1, compute cin 0..15
        if (k < 7) GATHER8(myj, 0);
        COMPUTE16(xw, wk, 0);
        if (k < 7) STORE8(xn, 0);

        // phase B: gather rows 8..15 of k+1, compute cin 16..31
        if (k < 7) GATHER8(myj, 8);
        if (k < 6) myj_nxt = IDX[(size_t)(k + 2) * N_ACT + rowc];
        COMPUTE16(xw, wk, 16);
        if (k < 7) STORE8(xn, 8);
    }

    // ---- epilogue: stats + store. lane owns rows rg*4..+3, couts cg*4..+3 ----
    const int rbase = wbase + (rg << 2);
    float s[4], sq[4];
#pragma unroll
    for (int j = 0; j < 4; j++) { s[j] = 0.f; sq[j] = 0.f; }
#pragma unroll
    for (int r = 0; r < 4; r++) {
        if (rbase + r < N_ACT) {
#pragma unroll
            for (int p = 0; p < 2; p++) {
                float2 f = unpack2(acc[r * 2 + p]);
                s [2*p]   += f.x;  sq[2*p]   += f.x * f.x;
                s [2*p+1] += f.y;  sq[2*p+1] += f.y * f.y;
            }
        }
    }
    // reduce over the 4 row-groups (lane xor 8,16 varies rg only)
#pragma unroll
    for (int off = 8; off <= 16; off <<= 1) {
#pragma unroll
        for (int j = 0; j < 4; j++) {
            s [j] += __shfl_xor_sync(0xffffffffu, s [j], off);
            sq[j] += __shfl_xor_sync(0xffffffffu, sq[j], off);
        }
    }
    if (rg == 0) {
#pragma unroll
        for (int j = 0; j < 4; j++) {
            red[0][warp][cg * 4 + j] = s[j];
            red[1][warp][cg * 4 + j] = sq[j];
        }
    }

    // store H: per row, 4 contiguous floats -> 1 STG.128
#pragma unroll
    for (int r = 0; r < 4; r++) {
        int r0 = rbase + r;
        if (r0 < N_ACT) {
            float2 f0 = unpack2(acc[r*2+0]), f1 = unpack2(acc[r*2+1]);
            *(float4*)(H + (size_t)r0 * 32 + (cg << 2)) =
                make_float4(f0.x, f0.y, f1.x, f1.y);
        }
    }

    __syncthreads();
    if (warp == 0) {
        float ts = 0.f, tq = 0.f;
#pragma unroll
        for (int w = 0; w < 8; w++) { ts += red[0][w][lane]; tq += red[1][w][lane]; }
        part[(size_t)lane        * NB_CONV + blockIdx.x] = ts;
        part[(size_t)(32 + lane) * NB_CONV + blockIdx.x] = tq;
    }
#undef GATHER8
#undef STORE8
#undef COMPUTE16
}

// ---------------- reduce: 64 blocks, block c sums its stat row (coalesced) ----
__global__ void reduce_kernel(int which)
{
    const float* part = which ? g_part2 : g_part1;
    float*       stat = which ? g_stat2 : g_stat1;

    const float* row = part + (size_t)blockIdx.x * NB_CONV;
    float s = 0.f;
#pragma unroll 4
    for (int i = threadIdx.x; i < NB_CONV; i += 256) s += row[i];

    __shared__ float sh[256];
    sh[threadIdx.x] = s;
    __syncthreads();
#pragma unroll
    for (int o = 128; o > 0; o >>= 1) {
        if (threadIdx.x < o) sh[threadIdx.x] += sh[threadIdx.x + o];
        __syncthreads();
    }
    if (threadIdx.x == 0) stat[blockIdx.x] = sh[0];
}

// ---------------- coefs: a = g*rsqrt(var+eps), c = b - mean*a ----------------
__global__ void coef_kernel(const float* __restrict__ gamma,
                            const float* __restrict__ beta, int which)
{
    const float* stat = which ? g_stat2 : g_stat1;
    float*       coef = which ? g_coef2 : g_coef1;
    int c = threadIdx.x;   // 32 threads
    float mean = stat[c] / (float)N_ACT;
    float var  = fmaxf(stat[32 + c] / (float)N_ACT - mean * mean, 0.f);
    float a    = gamma[c] * rsqrtf(var + BN_EPS);
    coef[c]      = a;
    coef[32 + c] = beta[c] - mean * a;
}

// ---------------- bn2 + residual add -> out ----------------
__global__ void final_kernel(const float* __restrict__ X, float* __restrict__ O)
{
    int i4 = blockIdx.x * 256 + threadIdx.x;
    int cb = i4 & 7;
    float4 a = ((const float4*)g_coef2)[cb];
    float4 c = ((const float4*)g_coef2)[8 + cb];
    float4 v = ((const float4*)g_h2)[i4];
    float4 x = ((const float4*)X)[i4];
    float4 o;
    o.x = fmaf(v.x, a.x, c.x) + x.x;
    o.y = fmaf(v.y, a.y, c.y) + x.y;
    o.z = fmaf(v.z, a.z, c.z) + x.z;
    o.w = fmaf(v.w, a.w, c.w) + x.w;
    ((float4*)O)[i4] = o;
}

extern "C" void kernel_launch(void* const* d_in, const int* in_sizes, int n_in,
                              void* d_out, int out_size)
{
    const float* x   = (const float*)d_in[0];
    const int*   idx = (const int*)  d_in[1];
    const float* W1  = (const float*)d_in[2];
    const float* g1  = (const float*)d_in[3];
    const float* b1  = (const float*)d_in[4];
    const float* W2  = (const float*)d_in[5];
    const float* g2  = (const float*)d_in[6];
    const float* b2  = (const float*)d_in[7];
    float* out = (float*)d_out;

    conv_kernel<0><<<NB_CONV, 256>>>(x, idx, W1);   // h1 = conv1(x), partials1
    reduce_kernel <<<64, 256>>>(0);                 // stat1
    coef_kernel   <<<1, 32>>>(g1, b1, 0);           // coef1
    conv_kernel<1><<<NB_CONV, 256>>>(x, idx, W2);   // h2 = conv2(bn1relu(h1)), partials2
    reduce_kernel <<<64, 256>>>(1);                 // stat2
    coef_kernel   <<<1, 32>>>(g2, b2, 1);           // coef2
    final_kernel  <<<NB_ELT, 256>>>(x, out);        // out = bn2(h2) + x
}

// round 8
// speedup vs baseline: 1.1980x; 1.0036x over previous
#include <cuda_runtime.h>
#include <cstdint>

#define N_ACT   1500000
#define ROWS_PB 128                                 // 8 warps x 16 rows
#define NB_CONV ((N_ACT + ROWS_PB - 1) / ROWS_PB)   // 11719 blocks
#define NB_ELT  ((N_ACT * 8) / 256)                 // N*32 floats / 4 per thread / 256
#define BN_EPS  1e-5f
#define XS      20                                  // smem stride (floats) per cin

// ---------------- scratch (no allocations allowed) ----------------
__device__ float g_h1[(size_t)N_ACT * 32];     // conv1 raw output
__device__ float g_h2[(size_t)N_ACT * 32];     // conv2 raw output
__device__ float g_part1[64 * NB_CONV];        // transposed: [stat][block]
__device__ float g_part2[64 * NB_CONV];
__device__ float g_stat1[64];                  // summed stats [sum(32), sumsq(32)]
__device__ float g_stat2[64];
__device__ float g_coef1[64];                  // [a(32), c(32)] : y = a*h + c
__device__ float g_coef2[64];

// ---------------- f32x2 helpers (Blackwell packed fp32) ----------------
__device__ __forceinline__ unsigned long long splat2(float w) {
    unsigned long long r;
    asm("mov.b64 %0, {%1, %1};" : "=l"(r) : "f"(w));
    return r;
}
__device__ __forceinline__ unsigned long long pack2(float lo, float hi) {
    unsigned long long r;
    asm("mov.b64 %0, {%1, %2};" : "=l"(r) : "f"(lo), "f"(hi));
    return r;
}
__device__ __forceinline__ float2 unpack2(unsigned long long v) {
    float2 f;
    asm("mov.b64 {%0, %1}, %2;" : "=f"(f.x), "=f"(f.y) : "l"(v));
    return f;
}
__device__ __forceinline__ void fma2(unsigned long long& acc,
                                     unsigned long long x,
                                     unsigned long long w) {
    asm("fma.rn.f32x2 %0, %1, %2, %0;" : "+l"(acc) : "l"(x), "l"(w));
}

// ---------------- conv: H[i] = sum_k gather(X, idx[k]) @ W[k] ----------------
// Warp tile: 16 rows x 32 cout. lane = rg*8+cg: rg = 4-row group, cg = 4-cout group.
// acc[r*2+p] (f32x2): row rbase+r, couts cg*4+2p, cg*4+2p+1.
// Gather (lane = cin) pipelined one k ahead into a double-buffered smem tile.
template<int WHICH>
__global__ __launch_bounds__(256, 4) void conv_kernel(
    const float* __restrict__ Xin, const int* __restrict__ IDX,
    const float* __restrict__ Wg)
{
    const float* X    = WHICH ? g_h1    : Xin;
    float*       H    = WHICH ? g_h2    : g_h1;
    float*       part = WHICH ? g_part2 : g_part1;

    // double-buffered per-warp transposed tile: [cin][row], stride XS floats
    __shared__ __align__(16) float sX[2][8][32 * XS];   // 40960 B
    __shared__ float red[2][8][32];                     //  2048 B

    const int tid   = threadIdx.x;
    const int warp  = tid >> 5;
    const int lane  = tid & 31;
    const int rg    = lane >> 3;            // rows [rg*4, rg*4+4)
    const int cg    = lane & 7;             // couts [cg*4, cg*4+4)
    const int wbase = blockIdx.x * ROWS_PB + warp * 16;

    float* xw0 = sX[0][warp];
    float* xw1 = sX[1][warp];

    // bn1+relu coefs for the fused gather transform (lane == channel)
    float a_bn = 0.f, c_bn = 0.f;
    if (WHICH) { a_bn = g_coef1[lane]; c_bn = g_coef1[32 + lane]; }

    unsigned long long acc[8];
#pragma unroll
    for (int i = 0; i < 8; i++) acc[i] = 0ULL;

    // idx row for this lane (lanes 16-31 duplicate 0-15); clamp keeps tail legal
    const int rowc = min(wbase + (lane & 15), N_ACT - 1);

    float vals[8];

#define GATHER8(MYJ, RB)                                                  \
    {                                                                     \
        _Pragma("unroll")                                                 \
        for (int r = 0; r < 8; r++) {                                     \
            int j = __shfl_sync(0xffffffffu, (MYJ), (RB) + r);            \
            float t = 0.f;                                                \
            if (j < N_ACT) {                                              \
                t = X[(size_t)j * 32 + lane];                             \
                if (WHICH) t = fmaxf(fmaf(t, a_bn, c_bn), 0.f);           \
            }                                                             \
            vals[r] = t;                                                  \
        }                                                                 \
    }
#define STORE8(DST, RB)                                                   \
    {                                                                     \
        *(float4*)((DST) + lane * XS + (RB))     =                        \
            make_float4(vals[0], vals[1], vals[2], vals[3]);              \
        *(float4*)((DST) + lane * XS + (RB) + 4) =                        \
            make_float4(vals[4], vals[5], vals[6], vals[7]);              \
    }
#define COMPUTE16(SRC, WK, CB)                                            \
    {                                                                     \
        _Pragma("unroll")                                                 \
        for (int ci = 0; ci < 16; ci++) {                                 \
            const int c = (CB) + ci;                                      \
            float4 xv = *(const float4*)((SRC) + c * XS + (rg << 2));     \
            float4 wv = *(const float4*)((WK) + c * 32 + (cg << 2));      \
            unsigned long long wp0 = pack2(wv.x, wv.y);                   \
            unsigned long long wp1 = pack2(wv.z, wv.w);                   \
            unsigned long long xs;                                        \
            xs = splat2(xv.x); fma2(acc[0], xs, wp0); fma2(acc[1], xs, wp1); \
            xs = splat2(xv.y); fma2(acc[2], xs, wp0); fma2(acc[3], xs, wp1); \
            xs = splat2(xv.z); fma2(acc[4], xs, wp0); fma2(acc[5], xs, wp1); \
            xs = splat2(xv.w); fma2(acc[6], xs, wp0); fma2(acc[7], xs, wp1); \
        }                                                                 \
    }

    // ---- prologue: gather k=0 into buf0 (full latency exposed once) ----
    int myj_cur = IDX[rowc];                       // idx for k=0
    GATHER8(myj_cur, 0); STORE8(xw0, 0);
    GATHER8(myj_cur, 8); STORE8(xw0, 8);
    int myj_nxt = IDX[(size_t)N_ACT + rowc];       // idx for k=1

#pragma unroll 1
    for (int k = 0; k < 8; k++) {
        __syncwarp();                              // buf[k&1] fully written
        const float* xw = (k & 1) ? xw1 : xw0;
        float*       xn = (k & 1) ? xw0 : xw1;
        const float* wk = Wg + k * 1024;
        const int    myj = myj_nxt;                // idx for k+1 (ready)

        // phase A: launch gather LDGs rows 0..7 of k+1, compute cin 0..15
        if (k < 7) GATHER8(myj, 0);
        COMPUTE16(xw, wk, 0);
        if (k < 7) STORE8(xn, 0);

        // phase B: gather rows 8..15 of k+1, compute cin 16..31
        if (k < 7) GATHER8(myj, 8);
        if (k < 6) myj_nxt = IDX[(size_t)(k + 2) * N_ACT + rowc];
        COMPUTE16(xw, wk, 16);
        if (k < 7) STORE8(xn, 8);
    }

    // ---- epilogue: stats + store. lane owns rows rg*4..+3, couts cg*4..+3 ----
    const int rbase = wbase + (rg << 2);
    float s[4], sq[4];
#pragma unroll
    for (int j = 0; j < 4; j++) { s[j] = 0.f; sq[j] = 0.f; }
#pragma unroll
    for (int r = 0; r < 4; r++) {
        if (rbase + r < N_ACT) {
#pragma unroll
            for (int p = 0; p < 2; p++) {
                float2 f = unpack2(acc[r * 2 + p]);
                s [2*p]   += f.x;  sq[2*p]   += f.x * f.x;
                s [2*p+1] += f.y;  sq[2*p+1] += f.y * f.y;
            }
        }
    }
    // reduce over the 4 row-groups (lane xor 8,16 varies rg only)
#pragma unroll
    for (int off = 8; off <= 16; off <<= 1) {
#pragma unroll
        for (int j = 0; j < 4; j++) {
            s [j] += __shfl_xor_sync(0xffffffffu, s [j], off);
            sq[j] += __shfl_xor_sync(0xffffffffu, sq[j], off);
        }
    }
    if (rg == 0) {
#pragma unroll
        for (int j = 0; j < 4; j++) {
            red[0][warp][cg * 4 + j] = s[j];
            red[1][warp][cg * 4 + j] = sq[j];
        }
    }

    // store H: per row, 4 contiguous floats -> 1 STG.128
#pragma unroll
    for (int r = 0; r < 4; r++) {
        int r0 = rbase + r;
        if (r0 < N_ACT) {
            float2 f0 = unpack2(acc[r*2+0]), f1 = unpack2(acc[r*2+1]);
            *(float4*)(H + (size_t)r0 * 32 + (cg << 2)) =
                make_float4(f0.x, f0.y, f1.x, f1.y);
        }
    }

    __syncthreads();
    if (warp == 0) {
        float ts = 0.f, tq = 0.f;
#pragma unroll
        for (int w = 0; w < 8; w++) { ts += red[0][w][lane]; tq += red[1][w][lane]; }
        part[(size_t)lane        * NB_CONV + blockIdx.x] = ts;
        part[(size_t)(32 + lane) * NB_CONV + blockIdx.x] = tq;
    }
#undef GATHER8
#undef STORE8
#undef COMPUTE16
}

// ---------------- reduce: 64 blocks, block c sums its stat row (coalesced) ----
__global__ void reduce_kernel(int which)
{
    const float* part = which ? g_part2 : g_part1;
    float*       stat = which ? g_stat2 : g_stat1;

    const float* row = part + (size_t)blockIdx.x * NB_CONV;
    float s = 0.f;
#pragma unroll 4
    for (int i = threadIdx.x; i < NB_CONV; i += 256) s += row[i];

    __shared__ float sh[256];
    sh[threadIdx.x] = s;
    __syncthreads();
#pragma unroll
    for (int o = 128; o > 0; o >>= 1) {
        if (threadIdx.x < o) sh[threadIdx.x] += sh[threadIdx.x + o];
        __syncthreads();
    }
    if (threadIdx.x == 0) stat[blockIdx.x] = sh[0];
}

// ---------------- coefs: a = g*rsqrt(var+eps), c = b - mean*a ----------------
__global__ void coef_kernel(const float* __restrict__ gamma,
                            const float* __restrict__ beta, int which)
{
    const float* stat = which ? g_stat2 : g_stat1;
    float*       coef = which ? g_coef2 : g_coef1;
    int c = threadIdx.x;   // 32 threads
    float mean = stat[c] / (float)N_ACT;
    float var  = fmaxf(stat[32 + c] / (float)N_ACT - mean * mean, 0.f);
    float a    = gamma[c] * rsqrtf(var + BN_EPS);
    coef[c]      = a;
    coef[32 + c] = beta[c] - mean * a;
}

// ---------------- bn2 + residual add -> out ----------------
__global__ void final_kernel(const float* __restrict__ X, float* __restrict__ O)
{
    int i4 = blockIdx.x * 256 + threadIdx.x;
    int cb = i4 & 7;
    float4 a = ((const float4*)g_coef2)[cb];
    float4 c = ((const float4*)g_coef2)[8 + cb];
    float4 v = ((const float4*)g_h2)[i4];
    float4 x = ((const float4*)X)[i4];
    float4 o;
    o.x = fmaf(v.x, a.x, c.x) + x.x;
    o.y = fmaf(v.y, a.y, c.y) + x.y;
    o.z = fmaf(v.z, a.z, c.z) + x.z;
    o.w = fmaf(v.w, a.w, c.w) + x.w;
    ((float4*)O)[i4] = o;
}

extern "C" void kernel_launch(void* const* d_in, const int* in_sizes, int n_in,
                              void* d_out, int out_size)
{
    const float* x   = (const float*)d_in[0];
    const int*   idx = (const int*)  d_in[1];
    const float* W1  = (const float*)d_in[2];
    const float* g1  = (const float*)d_in[3];
    const float* b1  = (const float*)d_in[4];
    const float* W2  = (const float*)d_in[5];
    const float* g2  = (const float*)d_in[6];
    const float* b2  = (const float*)d_in[7];
    float* out = (float*)d_out;

    conv_kernel<0><<<NB_CONV, 256>>>(x, idx, W1);   // h1 = conv1(x), partials1
    reduce_kernel <<<64, 256>>>(0);                 // stat1
    coef_kernel   <<<1, 32>>>(g1, b1, 0);           // coef1
    conv_kernel<1><<<NB_CONV, 256>>>(x, idx, W2);   // h2 = conv2(bn1relu(h1)), partials2
    reduce_kernel <<<64, 256>>>(1);                 // stat2
    coef_kernel   <<<1, 32>>>(g2, b2, 1);           // coef2
    final_kernel  <<<NB_ELT, 256>>>(x, out);        // out = bn2(h2) + x
}

// round 10
// speedup vs baseline: 1.7886x; 1.4930x over previous
#include <cuda_runtime.h>
#include <cstdint>

#define N_ACT   1500000
#define ROWS_PB 128                                 // 8 warps x 16 rows
#define NB_CONV ((N_ACT + ROWS_PB - 1) / ROWS_PB)   // 11719 blocks
#define NB_ELT  ((N_ACT * 8) / 256)
#define BN_EPS  1e-5f

// ---------------- scratch (no allocations allowed) ----------------
__device__ float g_h1[(size_t)N_ACT * 32];
__device__ float g_h2[(size_t)N_ACT * 32];
__device__ uint2 g_Wf[2][4096];                // fragment-ready W: [k][s*4+t][lane]
__device__ float g_part1[64 * NB_CONV];        // transposed: [stat][block]
__device__ float g_part2[64 * NB_CONV];
__device__ float g_stat1[64], g_stat2[64];
__device__ float g_coef1[64], g_coef2[64];

__device__ __forceinline__ uint32_t f2tf32(float f) {
    uint32_t u;
    asm("cvt.rna.tf32.f32 %0, %1;" : "=r"(u) : "f"(f));
    return u;
}
__device__ __forceinline__ void mma_tf32(float* d, const uint32_t* a, uint2 b) {
    asm volatile(
        "mma.sync.aligned.m16n8k8.row.col.f32.tf32.tf32.f32 "
        "{%0,%1,%2,%3}, {%4,%5,%6,%7}, {%8,%9}, {%0,%1,%2,%3};"
        : "+f"(d[0]), "+f"(d[1]), "+f"(d[2]), "+f"(d[3])
        : "r"(a[0]), "r"(a[1]), "r"(a[2]), "r"(a[3]), "r"(b.x), "r"(b.y));
}

// ---- W prep: W[k][cin][cout] -> tf32 fragments for mma.m16n8k8.row.col ----
// b0: cin = s*8 + tig, cout = t*8 + g ; b1: cin + 4.  8 blocks x 512 threads.
__global__ void prep_w(const float* __restrict__ W, int which)
{
    int k = blockIdx.x, tt = threadIdx.x;
    int lane = tt & 31, st = tt >> 5;       // st = s*4 + t
    int s = st >> 2;
    int cin0 = s * 8 + (lane & 3);
    int cout = (st & 3) * 8 + (lane >> 2);
    uint2 v;
    v.x = f2tf32(W[k * 1024 + cin0 * 32 + cout]);
    v.y = f2tf32(W[k * 1024 + (cin0 + 4) * 32 + cout]);
    g_Wf[which][k * 512 + st * 32 + lane] = v;
}

// ---------------- conv: H[i] = sum_k gather(X, idx[k]) @ W[k] ----------------
// Warp tile 16 rows x 32 couts via 4x mma.m16n8k8 (tf32). Gather coalesced via
// shfl, tf32-converted into per-warp double-buffered smem [row][cin], stride 36
// (conflict-free for both STS and A-fragment LDS).
template<int WHICH>
__global__ __launch_bounds__(256, 4) void conv_mma(
    const float* __restrict__ Xin, const int* __restrict__ IDX)
{
    const float* X    = WHICH ? g_h1    : Xin;
    float*       H    = WHICH ? g_h2    : g_h1;
    float*       part = WHICH ? g_part2 : g_part1;
    const uint2* Wf   = &g_Wf[WHICH][0];

    __shared__ uint32_t sX[2][8][16 * 36];   // 36864 B
    __shared__ float red[2][8][32];          //  2048 B

    const int tid   = threadIdx.x;
    const int warp  = tid >> 5;
    const int lane  = tid & 31;
    const int g     = lane >> 2;             // mma groupID
    const int tig   = lane & 3;              // mma thread-in-group
    const int wrow  = warp * 16;
    const int base  = blockIdx.x * ROWS_PB;

    float a_bn = 0.f, c_bn = 0.f;
    if (WHICH) { a_bn = g_coef1[lane]; c_bn = g_coef1[32 + lane]; }

    float acc[4][4];
#pragma unroll
    for (int t = 0; t < 4; t++)
#pragma unroll
        for (int i = 0; i < 4; i++) acc[t][i] = 0.f;

    const int rowc = min(base + wrow + (lane & 15), N_ACT - 1);
    uint32_t vals[8];

#define LOAD8(MYJ, RB)                                                     \
    {                                                                      \
        _Pragma("unroll")                                                  \
        for (int r = 0; r < 8; r++) {                                      \
            int j = __shfl_sync(0xffffffffu, (MYJ), (RB) + r);             \
            float t = 0.f;                                                 \
            if (j < N_ACT) {                                               \
                t = X[(size_t)j * 32 + lane];                              \
                if (WHICH) t = fmaxf(fmaf(t, a_bn, c_bn), 0.f);            \
            }                                                              \
            vals[r] = f2tf32(t);                                           \
        }                                                                  \
    }
#define STORE8(BUF, RB)                                                    \
    {                                                                      \
        _Pragma("unroll")                                                  \
        for (int r = 0; r < 8; r++)                                        \
            sX[BUF][warp][((RB) + r) * 36 + lane] = vals[r];               \
    }
#define COMPUTE_S(BUF, K, S)                                               \
    {                                                                      \
        const uint32_t* xw = &sX[BUF][warp][0];                            \
        uint32_t afr[4];                                                   \
        afr[0] = xw[g * 36 + (S) * 8 + tig];                               \
        afr[1] = xw[(g + 8) * 36 + (S) * 8 + tig];                         \
        afr[2] = xw[g * 36 + (S) * 8 + tig + 4];                           \
        afr[3] = xw[(g + 8) * 36 + (S) * 8 + tig + 4];                     \
        const uint2* wp = Wf + (K) * 512 + (S) * 128 + lane;               \
        mma_tf32(acc[0], afr, wp[0]);                                      \
        mma_tf32(acc[1], afr, wp[32]);                                     \
        mma_tf32(acc[2], afr, wp[64]);                                     \
        mma_tf32(acc[3], afr, wp[96]);                                     \
    }

    // ---- prologue: gather k=0 into buf 0 (full latency exposed once) ----
    int myj_cur = IDX[rowc];
    LOAD8(myj_cur, 0); STORE8(0, 0);
    LOAD8(myj_cur, 8); STORE8(0, 8);
    int myj_nxt = IDX[(size_t)N_ACT + rowc];
    __syncwarp();

#pragma unroll 1
    for (int k = 0; k < 8; k++) {
        const int cur = k & 1, nxt = cur ^ 1;
        const int myj = myj_nxt;
        if (k < 6) myj_nxt = IDX[(size_t)(k + 2) * N_ACT + rowc];

        if (k < 7) LOAD8(myj, 0);            // LDGs fly under compute
        COMPUTE_S(cur, k, 0); COMPUTE_S(cur, k, 1);
        if (k < 7) STORE8(nxt, 0);
        if (k < 7) LOAD8(myj, 8);
        COMPUTE_S(cur, k, 2); COMPUTE_S(cur, k, 3);
        if (k < 7) STORE8(nxt, 8);
        __syncwarp();                        // nxt written, cur reads done
    }
#undef LOAD8
#undef STORE8
#undef COMPUTE_S

    // ---- epilogue: H store + BN partials from D fragments ----
    // frag (t): c0=(row g, col 8t+2tig), c1=(g, +1), c2=(g+8, col), c3=(g+8, +1)
    const int r0 = base + wrow + g, r1 = r0 + 8;
    const bool v0 = r0 < N_ACT, v1 = r1 < N_ACT;
    float s0[4], s1[4], q0[4], q1[4];
#pragma unroll
    for (int t = 0; t < 4; t++) {
        float c0 = acc[t][0], c1 = acc[t][1], c2 = acc[t][2], c3 = acc[t][3];
        int col = t * 8 + tig * 2;
        if (v0) *(float2*)(H + (size_t)r0 * 32 + col) = make_float2(c0, c1);
        if (v1) *(float2*)(H + (size_t)r1 * 32 + col) = make_float2(c2, c3);
        s0[t] = (v0 ? c0 : 0.f) + (v1 ? c2 : 0.f);
        q0[t] = (v0 ? c0 * c0 : 0.f) + (v1 ? c2 * c2 : 0.f);
        s1[t] = (v0 ? c1 : 0.f) + (v1 ? c3 : 0.f);
        q1[t] = (v0 ? c1 * c1 : 0.f) + (v1 ? c3 * c3 : 0.f);
    }
#pragma unroll
    for (int off = 4; off <= 16; off <<= 1) {
#pragma unroll
        for (int t = 0; t < 4; t++) {
            s0[t] += __shfl_xor_sync(0xffffffffu, s0[t], off);
            q0[t] += __shfl_xor_sync(0xffffffffu, q0[t], off);
            s1[t] += __shfl_xor_sync(0xffffffffu, s1[t], off);
            q1[t] += __shfl_xor_sync(0xffffffffu, q1[t], off);
        }
    }
    if (lane < 4) {                          // lane == tig, g == 0
#pragma unroll
        for (int t = 0; t < 4; t++) {
            red[0][warp][t * 8 + lane * 2]     = s0[t];
            red[0][warp][t * 8 + lane * 2 + 1] = s1[t];
            red[1][warp][t * 8 + lane * 2]     = q0[t];
            red[1][warp][t * 8 + lane * 2 + 1] = q1[t];
        }
    }
    __syncthreads();
    if (warp == 0) {
        float ts = 0.f, tq = 0.f;
#pragma unroll
        for (int w = 0; w < 8; w++) { ts += red[0][w][lane]; tq += red[1][w][lane]; }
        part[(size_t)lane        * NB_CONV + blockIdx.x] = ts;
        part[(size_t)(32 + lane) * NB_CONV + blockIdx.x] = tq;
    }
}

// ---------------- reduce: 64 blocks, block c sums its stat row ----------------
__global__ void reduce_kernel(int which)
{
    const float* part = which ? g_part2 : g_part1;
    float*       stat = which ? g_stat2 : g_stat1;
    const float* row  = part + (size_t)blockIdx.x * NB_CONV;
    float s = 0.f;
#pragma unroll 4
    for (int i = threadIdx.x; i < NB_CONV; i += 256) s += row[i];
    __shared__ float sh[256];
    sh[threadIdx.x] = s;
    __syncthreads();
#pragma unroll
    for (int o = 128; o > 0; o >>= 1) {
        if (threadIdx.x < o) sh[threadIdx.x] += sh[threadIdx.x + o];
        __syncthreads();
    }
    if (threadIdx.x == 0) stat[blockIdx.x] = sh[0];
}

__global__ void coef_kernel(const float* __restrict__ gamma,
                            const float* __restrict__ beta, int which)
{
    const float* stat = which ? g_stat2 : g_stat1;
    float*       coef = which ? g_coef2 : g_coef1;
    int c = threadIdx.x;
    float mean = stat[c] / (float)N_ACT;
    float var  = fmaxf(stat[32 + c] / (float)N_ACT - mean * mean, 0.f);
    float a    = gamma[c] * rsqrtf(var + BN_EPS);
    coef[c]      = a;
    coef[32 + c] = beta[c] - mean * a;
}

__global__ void final_kernel(const float* __restrict__ X, float* __restrict__ O)
{
    int i4 = blockIdx.x * 256 + threadIdx.x;
    int cb = i4 & 7;
    float4 a = ((const float4*)g_coef2)[cb];
    float4 c = ((const float4*)g_coef2)[8 + cb];
    float4 v = ((const float4*)g_h2)[i4];
    float4 x = ((const float4*)X)[i4];
    float4 o;
    o.x = fmaf(v.x, a.x, c.x) + x.x;
    o.y = fmaf(v.y, a.y, c.y) + x.y;
    o.z = fmaf(v.z, a.z, c.z) + x.z;
    o.w = fmaf(v.w, a.w, c.w) + x.w;
    ((float4*)O)[i4] = o;
}

extern "C" void kernel_launch(void* const* d_in, const int* in_sizes, int n_in,
                              void* d_out, int out_size)
{
    const float* x   = (const float*)d_in[0];
    const int*   idx = (const int*)  d_in[1];
    const float* W1  = (const float*)d_in[2];
    const float* g1  = (const float*)d_in[3];
    const float* b1  = (const float*)d_in[4];
    const float* W2  = (const float*)d_in[5];
    const float* g2  = (const float*)d_in[6];
    const float* b2  = (const float*)d_in[7];
    float* out = (float*)d_out;

    prep_w<<<8, 512>>>(W1, 0);
    prep_w<<<8, 512>>>(W2, 1);
    conv_mma<0><<<NB_CONV, 256>>>(x, idx);    // h1 = conv1(x), partials1
    reduce_kernel<<<64, 256>>>(0);
    coef_kernel  <<<1, 32>>>(g1, b1, 0);
    conv_mma<1><<<NB_CONV, 256>>>(x, idx);    // h2 = conv2(bn1relu(h1)), partials2
    reduce_kernel<<<64, 256>>>(1);
    coef_kernel  <<<1, 32>>>(g2, b2, 1);
    final_kernel <<<NB_ELT, 256>>>(x, out);   // out = bn2(h2) + x
}

// round 11
// speedup vs baseline: 3.0020x; 1.6784x over previous
#include <cuda_runtime.h>
#include <cuda_fp16.h>
#include <cstdint>

#define N_ACT   1500000
#define ROWS_PB 128                                 // 8 warps x 16 rows
#define NB_CONV ((N_ACT + ROWS_PB - 1) / ROWS_PB)   // 11719 blocks
#define NB_ELT  ((N_ACT * 8) / 256)
#define BN_EPS  1e-5f

// ---------------- scratch (no allocations allowed) ----------------
__device__ float g_h1[(size_t)N_ACT * 32];
__device__ float g_h2[(size_t)N_ACT * 32];
__device__ uint2 g_Wf[2][2048];                // fp16 B frags: [k][s*4+t][lane]
__device__ float g_part1[64 * NB_CONV];        // transposed: [stat][block]
__device__ float g_part2[64 * NB_CONV];
__device__ float g_stat1[64], g_stat2[64];
__device__ float g_coef1[64], g_coef2[64];

__device__ __forceinline__ uint32_t smem_u32(const void* p) {
    uint32_t a;
    asm("{ .reg .u64 t; cvta.to.shared.u64 t, %1; cvt.u32.u64 %0, t; }" : "=r"(a) : "l"(p));
    return a;
}
__device__ __forceinline__ uint32_t h2pack(float lo, float hi) {
    __half2 p = __floats2half2_rn(lo, hi);       // low = first arg
    return *reinterpret_cast<uint32_t*>(&p);
}
__device__ __forceinline__ void mma_f16(float* d, const uint32_t* a, uint2 b) {
    asm volatile(
        "mma.sync.aligned.m16n8k16.row.col.f32.f16.f16.f32 "
        "{%0,%1,%2,%3}, {%4,%5,%6,%7}, {%8,%9}, {%0,%1,%2,%3};"
        : "+f"(d[0]), "+f"(d[1]), "+f"(d[2]), "+f"(d[3])
        : "r"(a[0]), "r"(a[1]), "r"(a[2]), "r"(a[3]), "r"(b.x), "r"(b.y));
}
__device__ __forceinline__ void ldmx4(uint32_t* a, uint32_t addr) {
    asm volatile("ldmatrix.sync.aligned.m8n8.x4.shared.b16 {%0,%1,%2,%3}, [%4];"
        : "=r"(a[0]), "=r"(a[1]), "=r"(a[2]), "=r"(a[3]) : "r"(addr));
}

// ---- W prep: W[k][cin][cout] -> fp16 B fragments for mma.m16n8k16.row.col ----
// entry [k][s*4+t][lane]: b0 = {W[16s+2tig][8t+g], W[16s+2tig+1][8t+g]}, b1 = +8 cin
__global__ void prep_w(const float* __restrict__ W, int which)
{
    int k = blockIdx.x, tt = threadIdx.x;        // 8 blocks x 256 threads
    int lane = tt & 31, st = tt >> 5;            // st = s*4 + t
    int g = lane >> 2, tig = lane & 3;
    int cin0 = (st >> 2) * 16 + 2 * tig;
    int cout = (st & 3) * 8 + g;
    const float* wk = W + k * 1024;
    uint2 v;
    v.x = h2pack(wk[cin0 * 32 + cout],       wk[(cin0 + 1) * 32 + cout]);
    v.y = h2pack(wk[(cin0 + 8) * 32 + cout], wk[(cin0 + 9) * 32 + cout]);
    g_Wf[which][k * 256 + st * 32 + lane] = v;
}

// ---------------- conv: H[i] = sum_k gather(X, idx[k]) @ W[k] ----------------
// Warp tile 16 rows x 32 couts via 8x mma.m16n8k16 fp16 per k-offset.
// A tile in smem: 16 rows x 32 halfs (16 words), chunk-swizzled:
//   word(r, chunk, o) = r*16 + (chunk ^ ((r>>1)&3))*4 + o   -- conflict-free for
//   STS.64 gather writes and ldmatrix.x4 fragment reads (verified by hand).
template<int WHICH>
__global__ __launch_bounds__(256, 4) void conv_mma(
    const float* __restrict__ Xin, const int* __restrict__ IDX)
{
    const float* X    = WHICH ? g_h1    : Xin;
    float*       H    = WHICH ? g_h2    : g_h1;
    float*       part = WHICH ? g_part2 : g_part1;
    const uint2* Wf   = &g_Wf[WHICH][0];

    __shared__ uint32_t sH[2][8][256];           // 16 KB
    __shared__ float red[2][8][32];              //  2 KB

    const int tid   = threadIdx.x;
    const int warp  = tid >> 5;
    const int lane  = tid & 31;
    const int g     = lane >> 2;                 // mma groupID
    const int tig   = lane & 3;                  // mma thread-in-group
    const int wrow  = warp * 16;
    const int base  = blockIdx.x * ROWS_PB;

    // gather role: lane covers row (lane>>3)+4i, channels 4*c8..4*c8+3
    const int c8   = lane & 7;
    const int rsub = lane >> 3;

    float4 A4 = make_float4(0.f, 0.f, 0.f, 0.f), C4 = A4;
    if (WHICH) {
        A4 = ((const float4*)g_coef1)[c8];
        C4 = ((const float4*)g_coef1)[8 + c8];
    }

    float acc[4][4];
#pragma unroll
    for (int t = 0; t < 4; t++)
#pragma unroll
        for (int i = 0; i < 4; i++) acc[t][i] = 0.f;

    const int rowc = min(base + wrow + (lane & 15), N_ACT - 1);

    // ldmatrix per-thread addresses (mat order T00,T10,T01,T11)
    const int mat = lane >> 3;
    const int rr  = (lane & 7) + ((mat & 1) << 3);
    const int swz = (rr >> 1) & 3;
    const uint32_t w_s0 = rr * 16 + (((mat >> 1)       ^ swz) << 2);
    const uint32_t w_s1 = rr * 16 + (((2 + (mat >> 1)) ^ swz) << 2);
    const uint32_t ub[2] = { smem_u32(&sH[0][warp][0]), smem_u32(&sH[1][warp][0]) };

    float4 vv[4];

#define LOADK(MYJ)                                                          \
    {                                                                       \
        _Pragma("unroll")                                                   \
        for (int i = 0; i < 4; i++) {                                       \
            int j = __shfl_sync(0xffffffffu, (MYJ), rsub + 4 * i);          \
            float4 v = make_float4(0.f, 0.f, 0.f, 0.f);                     \
            if (j < N_ACT) {                                                \
                v = *(const float4*)(X + (size_t)j * 32 + c8 * 4);          \
                if (WHICH) {                                                \
                    v.x = fmaxf(fmaf(v.x, A4.x, C4.x), 0.f);                \
                    v.y = fmaxf(fmaf(v.y, A4.y, C4.y), 0.f);                \
                    v.z = fmaxf(fmaf(v.z, A4.z, C4.z), 0.f);                \
                    v.w = fmaxf(fmaf(v.w, A4.w, C4.w), 0.f);                \
                }                                                           \
            }                                                               \
            vv[i] = v;                                                      \
        }                                                                   \
    }
#define STOREK(BUF)                                                         \
    {                                                                       \
        _Pragma("unroll")                                                   \
        for (int i = 0; i < 4; i++) {                                       \
            int r = rsub + 4 * i;                                           \
            uint32_t w = r * 16 + ((((c8 >> 1) ^ ((r >> 1) & 3)) << 2)      \
                       | ((c8 & 1) << 1));                                  \
            uint2 h;                                                        \
            h.x = h2pack(vv[i].x, vv[i].y);                                 \
            h.y = h2pack(vv[i].z, vv[i].w);                                 \
            *(uint2*)&sH[BUF][warp][w] = h;                                 \
        }                                                                   \
    }
#define COMPUTE_S(UB, K, WS, S)                                             \
    {                                                                       \
        uint32_t afr[4];                                                    \
        ldmx4(afr, (UB) + (WS) * 4);                                        \
        const uint2* wp = Wf + (K) * 256 + (S) * 128 + lane;                \
        mma_f16(acc[0], afr, wp[0]);                                        \
        mma_f16(acc[1], afr, wp[32]);                                       \
        mma_f16(acc[2], afr, wp[64]);                                       \
        mma_f16(acc[3], afr, wp[96]);                                       \
    }

    // ---- prologue: gather k=0 into buf 0 (full latency exposed once) ----
    int myj_cur = IDX[rowc];
    LOADK(myj_cur); STOREK(0);
    int myj_nxt = IDX[(size_t)N_ACT + rowc];
    __syncwarp();

#pragma unroll 1
    for (int k = 0; k < 8; k++) {
        const int cur = k & 1, nxt = cur ^ 1;
        const int myj = myj_nxt;
        if (k < 6) myj_nxt = IDX[(size_t)(k + 2) * N_ACT + rowc];

        if (k < 7) LOADK(myj);               // 4x LDG.128 fly under compute
        COMPUTE_S(ub[cur], k, w_s0, 0);
        COMPUTE_S(ub[cur], k, w_s1, 1);
        if (k < 7) STOREK(nxt);
        __syncwarp();                        // nxt written, cur reads done
    }
#undef LOADK
#undef STOREK
#undef COMPUTE_S

    // ---- epilogue: H store + BN partials from D fragments ----
    // frag (t): c0=(row g, col 8t+2tig), c1=(g, +1), c2=(g+8, col), c3=(g+8, +1)
    const int r0 = base + wrow + g, r1 = r0 + 8;
    const bool v0 = r0 < N_ACT, v1 = r1 < N_ACT;
    float s0[4], s1[4], q0[4], q1[4];
#pragma unroll
    for (int t = 0; t < 4; t++) {
        float c0 = acc[t][0], c1 = acc[t][1], c2 = acc[t][2], c3 = acc[t][3];
        int col = t * 8 + tig * 2;
        if (v0) *(float2*)(H + (size_t)r0 * 32 + col) = make_float2(c0, c1);
        if (v1) *(float2*)(H + (size_t)r1 * 32 + col) = make_float2(c2, c3);
        s0[t] = (v0 ? c0 : 0.f) + (v1 ? c2 : 0.f);
        q0[t] = (v0 ? c0 * c0 : 0.f) + (v1 ? c2 * c2 : 0.f);
        s1[t] = (v0 ? c1 : 0.f) + (v1 ? c3 : 0.f);
        q1[t] = (v0 ? c1 * c1 : 0.f) + (v1 ? c3 * c3 : 0.f);
    }
#pragma unroll
    for (int off = 4; off <= 16; off <<= 1) {
#pragma unroll
        for (int t = 0; t < 4; t++) {
            s0[t] += __shfl_xor_sync(0xffffffffu, s0[t], off);
            q0[t] += __shfl_xor_sync(0xffffffffu, q0[t], off);
            s1[t] += __shfl_xor_sync(0xffffffffu, s1[t], off);
            q1[t] += __shfl_xor_sync(0xffffffffu, q1[t], off);
        }
    }
    if (lane < 4) {                          // lane == tig, g == 0
#pragma unroll
        for (int t = 0; t < 4; t++) {
            red[0][warp][t * 8 + lane * 2]     = s0[t];
            red[0][warp][t * 8 + lane * 2 + 1] = s1[t];
            red[1][warp][t * 8 + lane * 2]     = q0[t];
            red[1][warp][t * 8 + lane * 2 + 1] = q1[t];
        }
    }
    __syncthreads();
    if (warp == 0) {
        float ts = 0.f, tq = 0.f;
#pragma unroll
        for (int w = 0; w < 8; w++) { ts += red[0][w][lane]; tq += red[1][w][lane]; }
        part[(size_t)lane        * NB_CONV + blockIdx.x] = ts;
        part[(size_t)(32 + lane) * NB_CONV + blockIdx.x] = tq;
    }
}

// ---------------- reduce: 64 blocks, block c sums its stat row ----------------
__global__ void reduce_kernel(int which)
{
    const float* part = which ? g_part2 : g_part1;
    float*       stat = which ? g_stat2 : g_stat1;
    const float* row  = part + (size_t)blockIdx.x * NB_CONV;
    float s = 0.f;
#pragma unroll 4
    for (int i = threadIdx.x; i < NB_CONV; i += 256) s += row[i];
    __shared__ float sh[256];
    sh[threadIdx.x] = s;
    __syncthreads();
#pragma unroll
    for (int o = 128; o > 0; o >>= 1) {
        if (threadIdx.x < o) sh[threadIdx.x] += sh[threadIdx.x + o];
        __syncthreads();
    }
    if (threadIdx.x == 0) stat[blockIdx.x] = sh[0];
}

__global__ void coef_kernel(const float* __restrict__ gamma,
                            const float* __restrict__ beta, int which)
{
    const float* stat = which ? g_stat2 : g_stat1;
    float*       coef = which ? g_coef2 : g_coef1;
    int c = threadIdx.x;
    float mean = stat[c] / (float)N_ACT;
    float var  = fmaxf(stat[32 + c] / (float)N_ACT - mean * mean, 0.f);
    float a    = gamma[c] * rsqrtf(var + BN_EPS);
    coef[c]      = a;
    coef[32 + c] = beta[c] - mean * a;
}

__global__ void final_kernel(const float* __restrict__ X, float* __restrict__ O)
{
    int i4 = blockIdx.x * 256 + threadIdx.x;
    int cb = i4 & 7;
    float4 a = ((const float4*)g_coef2)[cb];
    float4 c = ((const float4*)g_coef2)[8 + cb];
    float4 v = ((const float4*)g_h2)[i4];
    float4 x = ((const float4*)X)[i4];
    float4 o;
    o.x = fmaf(v.x, a.x, c.x) + x.x;
    o.y = fmaf(v.y, a.y, c.y) + x.y;
    o.z = fmaf(v.z, a.z, c.z) + x.z;
    o.w = fmaf(v.w, a.w, c.w) + x.w;
    ((float4*)O)[i4] = o;
}

extern "C" void kernel_launch(void* const* d_in, const int* in_sizes, int n_in,
                              void* d_out, int out_size)
{
    const float* x   = (const float*)d_in[0];
    const int*   idx = (const int*)  d_in[1];
    const float* W1  = (const float*)d_in[2];
    const float* g1  = (const float*)d_in[3];
    const float* b1  = (const float*)d_in[4];
    const float* W2  = (const float*)d_in[5];
    const float* g2  = (const float*)d_in[6];
    const float* b2  = (const float*)d_in[7];
    float* out = (float*)d_out;

    prep_w<<<8, 256>>>(W1, 0);
    prep_w<<<8, 256>>>(W2, 1);
    conv_mma<0><<<NB_CONV, 256>>>(x, idx);    // h1 = conv1(x), partials1
    reduce_kernel<<<64, 256>>>(0);
    coef_kernel  <<<1, 32>>>(g1, b1, 0);
    conv_mma<1><<<NB_CONV, 256>>>(x, idx);    // h2 = conv2(bn1relu(h1)), partials2
    reduce_kernel<<<64, 256>>>(1);
    coef_kernel  <<<1, 32>>>(g2, b2, 1);
    final_kernel <<<NB_ELT, 256>>>(x, out);   // out = bn2(h2) + x
}

// round 12
// speedup vs baseline: 3.6228x; 1.2068x over previous
#include <cuda_runtime.h>
#include <cuda_fp16.h>
#include <cstdint>

#define N_ACT   1500000
#define ROWS_PB 128                                 // 8 warps x 16 rows
#define NB_CONV ((N_ACT + ROWS_PB - 1) / ROWS_PB)   // 11719 blocks
#define NB_ELT  ((N_ACT * 8) / 256)
#define BN_EPS  1e-5f

// ---------------- scratch (no allocations allowed) ----------------
__device__ __half g_h1h[(size_t)N_ACT * 32];   // conv1 out, fp16 (96MB: L2-friendly)
__device__ __half g_h2h[(size_t)N_ACT * 32];   // conv2 out, fp16
__device__ uint2  g_Wf[2][2048];               // fp16 B frags: [k][s*4+t][lane]
__device__ float  g_part1[64 * NB_CONV];       // transposed: [stat][block]
__device__ float  g_part2[64 * NB_CONV];
__device__ float  g_stat1[64], g_stat2[64];
__device__ float  g_coef1[64], g_coef2[64];

__device__ __forceinline__ uint32_t smem_u32(const void* p) {
    uint32_t a;
    asm("{ .reg .u64 t; cvta.to.shared.u64 t, %1; cvt.u32.u64 %0, t; }" : "=r"(a) : "l"(p));
    return a;
}
__device__ __forceinline__ uint32_t h2pack(float lo, float hi) {
    __half2 p = __floats2half2_rn(lo, hi);
    return *reinterpret_cast<uint32_t*>(&p);
}
__device__ __forceinline__ void mma_f16(float* d, const uint32_t* a, uint2 b) {
    asm volatile(
        "mma.sync.aligned.m16n8k16.row.col.f32.f16.f16.f32 "
        "{%0,%1,%2,%3}, {%4,%5,%6,%7}, {%8,%9}, {%0,%1,%2,%3};"
        : "+f"(d[0]), "+f"(d[1]), "+f"(d[2]), "+f"(d[3])
        : "r"(a[0]), "r"(a[1]), "r"(a[2]), "r"(a[3]), "r"(b.x), "r"(b.y));
}
__device__ __forceinline__ void ldmx4(uint32_t* a, uint32_t addr) {
    asm volatile("ldmatrix.sync.aligned.m8n8.x4.shared.b16 {%0,%1,%2,%3}, [%4];"
        : "=r"(a[0]), "=r"(a[1]), "=r"(a[2]), "=r"(a[3]) : "r"(addr));
}

// ---- W prep: W[k][cin][cout] -> fp16 B fragments for mma.m16n8k16.row.col ----
__global__ void prep_w(const float* __restrict__ W, int which)
{
    int k = blockIdx.x, tt = threadIdx.x;        // 8 blocks x 256 threads
    int lane = tt & 31, st = tt >> 5;            // st = s*4 + t
    int g = lane >> 2, tig = lane & 3;
    int cin0 = (st >> 2) * 16 + 2 * tig;
    int cout = (st & 3) * 8 + g;
    const float* wk = W + k * 1024;
    uint2 v;
    v.x = h2pack(wk[cin0 * 32 + cout],       wk[(cin0 + 1) * 32 + cout]);
    v.y = h2pack(wk[(cin0 + 8) * 32 + cout], wk[(cin0 + 9) * 32 + cout]);
    g_Wf[which][k * 256 + st * 32 + lane] = v;
}

// ---------------- conv: H[i] = sum_k gather(X, idx[k]) @ W[k] ----------------
// Warp tile 16 rows x 32 couts via 8x mma.m16n8k16 fp16 per k-offset.
// A tile: 16 rows x 32 halfs (16 words/row), chunk-XOR swizzle:
//   word(r, chunk, o) = r*16 + (chunk ^ ((r>>1)&3))*4 + o
// conflict-free for gather STS and ldmatrix.x4 reads.
// WHICH==0: gather fp32 x rows. WHICH==1: gather fp16 h1 rows + inline bn1relu.
template<int WHICH>
__global__ __launch_bounds__(256, 4) void conv_mma(
    const float* __restrict__ Xin, const int* __restrict__ IDX)
{
    __half*      H16  = WHICH ? g_h2h   : g_h1h;
    float*       part = WHICH ? g_part2 : g_part1;
    const uint2* Wf   = &g_Wf[WHICH][0];

    __shared__ uint32_t sH[2][8][256];           // 16 KB
    __shared__ float red[2][8][32];              //  2 KB

    const int tid   = threadIdx.x;
    const int warp  = tid >> 5;
    const int lane  = tid & 31;
    const int g     = lane >> 2;                 // mma groupID
    const int tig   = lane & 3;                  // mma thread-in-group
    const int wrow  = warp * 16;
    const int base  = blockIdx.x * ROWS_PB;

    // gather roles
    const int c8   = lane & 7;                   // conv1: 4-float chunk
    const int rsub = lane >> 3;                  // conv1: row strider (4 iters)
    const int q4   = lane & 3;                   // conv2: 8-half chunk
    const int rsub8 = lane >> 2;                 // conv2: row strider (2 iters)

    // bn1+relu coefs (fp16 pairs for conv2 gather channels q4*8 .. q4*8+7)
    __half2 abn[4], cbn[4];
    if (WHICH) {
#pragma unroll
        for (int m = 0; m < 4; m++) {
            abn[m] = __floats2half2_rn(g_coef1[q4 * 8 + 2 * m],
                                       g_coef1[q4 * 8 + 2 * m + 1]);
            cbn[m] = __floats2half2_rn(g_coef1[32 + q4 * 8 + 2 * m],
                                       g_coef1[32 + q4 * 8 + 2 * m + 1]);
        }
    }

    float acc[4][4];
#pragma unroll
    for (int t = 0; t < 4; t++)
#pragma unroll
        for (int i = 0; i < 4; i++) acc[t][i] = 0.f;

    const int rowc = min(base + wrow + (lane & 15), N_ACT - 1);

    // ldmatrix per-thread addresses (mat order T00,T10,T01,T11)
    const int mat = lane >> 3;
    const int rr  = (lane & 7) + ((mat & 1) << 3);
    const int swz = (rr >> 1) & 3;
    const uint32_t w_s0 = rr * 16 + (((mat >> 1)       ^ swz) << 2);
    const uint32_t w_s1 = rr * 16 + (((2 + (mat >> 1)) ^ swz) << 2);
    const uint32_t ub[2] = { smem_u32(&sH[0][warp][0]), smem_u32(&sH[1][warp][0]) };

    float4 vv[4];     // conv1 buffer
    uint4  hv[2];     // conv2 buffer

#define LOADK(MYJ)                                                          \
    {                                                                       \
        if constexpr (WHICH == 0) {                                         \
            _Pragma("unroll")                                               \
            for (int i = 0; i < 4; i++) {                                   \
                int j = __shfl_sync(0xffffffffu, (MYJ), rsub + 4 * i);      \
                float4 v = make_float4(0.f, 0.f, 0.f, 0.f);                 \
                if (j < N_ACT)                                              \
                    v = *(const float4*)(Xin + (size_t)j * 32 + c8 * 4);    \
                vv[i] = v;                                                  \
            }                                                               \
        } else {                                                            \
            const __half2 hz = __floats2half2_rn(0.f, 0.f);                 \
            _Pragma("unroll")                                               \
            for (int i = 0; i < 2; i++) {                                   \
                int j = __shfl_sync(0xffffffffu, (MYJ), rsub8 + 8 * i);     \
                uint4 v = make_uint4(0u, 0u, 0u, 0u);                       \
                if (j < N_ACT) {                                            \
                    v = *(const uint4*)(g_h1h + (size_t)j * 32 + q4 * 8);   \
                    __half2* hp = (__half2*)&v;                             \
                    _Pragma("unroll")                                       \
                    for (int m = 0; m < 4; m++)                             \
                        hp[m] = __hmax2(__hfma2(hp[m], abn[m], cbn[m]), hz);\
                }                                                           \
                hv[i] = v;                                                  \
            }                                                               \
        }                                                                   \
    }
#define STOREK(BUF)                                                         \
    {                                                                       \
        if constexpr (WHICH == 0) {                                         \
            _Pragma("unroll")                                               \
            for (int i = 0; i < 4; i++) {                                   \
                int r = rsub + 4 * i;                                       \
                uint32_t w = r * 16 + ((((c8 >> 1) ^ ((r >> 1) & 3)) << 2)  \
                           | ((c8 & 1) << 1));                              \
                uint2 h;                                                    \
                h.x = h2pack(vv[i].x, vv[i].y);                             \
                h.y = h2pack(vv[i].z, vv[i].w);                             \
                *(uint2*)&sH[BUF][warp][w] = h;                             \
            }                                                               \
        } else {                                                            \
            _Pragma("unroll")                                               \
            for (int i = 0; i < 2; i++) {                                   \
                int r = rsub8 + 8 * i;                                      \
                uint32_t w = r * 16 + (((q4 ^ ((r >> 1) & 3))) << 2);       \
                *(uint4*)&sH[BUF][warp][w] = hv[i];                         \
            }                                                               \
        }                                                                   \
    }
#define COMPUTE_S(UB, K, WS, S)                                             \
    {                                                                       \
        uint32_t afr[4];                                                    \
        ldmx4(afr, (UB) + (WS) * 4);                                        \
        const uint2* wp = Wf + (K) * 256 + (S) * 128 + lane;                \
        mma_f16(acc[0], afr, wp[0]);                                        \
        mma_f16(acc[1], afr, wp[32]);                                       \
        mma_f16(acc[2], afr, wp[64]);                                       \
        mma_f16(acc[3], afr, wp[96]);                                       \
    }

    // ---- prologue: gather k=0 into buf 0 (full latency exposed once) ----
    int myj_cur = IDX[rowc];
    LOADK(myj_cur); STOREK(0);
    int myj_nxt = IDX[(size_t)N_ACT + rowc];
    __syncwarp();

#pragma unroll 1
    for (int k = 0; k < 8; k++) {
        const int cur = k & 1, nxt = cur ^ 1;
        const int myj = myj_nxt;
        if (k < 6) myj_nxt = IDX[(size_t)(k + 2) * N_ACT + rowc];

        if (k < 7) LOADK(myj);               // gather LDGs fly under compute
        COMPUTE_S(ub[cur], k, w_s0, 0);
        COMPUTE_S(ub[cur], k, w_s1, 1);
        if (k < 7) STOREK(nxt);
        __syncwarp();                        // nxt written, cur reads done
    }
#undef LOADK
#undef STOREK
#undef COMPUTE_S

    // ---- epilogue: fp16 H store + fp32 BN partials from D fragments ----
    const int r0 = base + wrow + g, r1 = r0 + 8;
    const bool v0 = r0 < N_ACT, v1 = r1 < N_ACT;
    float s0[4], s1[4], q0[4], q1[4];
#pragma unroll
    for (int t = 0; t < 4; t++) {
        float c0 = acc[t][0], c1 = acc[t][1], c2 = acc[t][2], c3 = acc[t][3];
        int col = t * 8 + tig * 2;
        if (v0) *(__half2*)(H16 + (size_t)r0 * 32 + col) = __floats2half2_rn(c0, c1);
        if (v1) *(__half2*)(H16 + (size_t)r1 * 32 + col) = __floats2half2_rn(c2, c3);
        s0[t] = (v0 ? c0 : 0.f) + (v1 ? c2 : 0.f);
        q0[t] = (v0 ? c0 * c0 : 0.f) + (v1 ? c2 * c2 : 0.f);
        s1[t] = (v0 ? c1 : 0.f) + (v1 ? c3 : 0.f);
        q1[t] = (v0 ? c1 * c1 : 0.f) + (v1 ? c3 * c3 : 0.f);
    }
#pragma unroll
    for (int off = 4; off <= 16; off <<= 1) {
#pragma unroll
        for (int t = 0; t < 4; t++) {
            s0[t] += __shfl_xor_sync(0xffffffffu, s0[t], off);
            q0[t] += __shfl_xor_sync(0xffffffffu, q0[t], off);
            s1[t] += __shfl_xor_sync(0xffffffffu, s1[t], off);
            q1[t] += __shfl_xor_sync(0xffffffffu, q1[t], off);
        }
    }
    if (lane < 4) {                          // lane == tig, g == 0
#pragma unroll
        for (int t = 0; t < 4; t++) {
            red[0][warp][t * 8 + lane * 2]     = s0[t];
            red[0][warp][t * 8 + lane * 2 + 1] = s1[t];
            red[1][warp][t * 8 + lane * 2]     = q0[t];
            red[1][warp][t * 8 + lane * 2 + 1] = q1[t];
        }
    }
    __syncthreads();
    if (warp == 0) {
        float ts = 0.f, tq = 0.f;
#pragma unroll
        for (int w = 0; w < 8; w++) { ts += red[0][w][lane]; tq += red[1][w][lane]; }
        part[(size_t)lane        * NB_CONV + blockIdx.x] = ts;
        part[(size_t)(32 + lane) * NB_CONV + blockIdx.x] = tq;
    }
}

// ---------------- reduce: 64 blocks, block c sums its stat row ----------------
__global__ void reduce_kernel(int which)
{
    const float* part = which ? g_part2 : g_part1;
    float*       stat = which ? g_stat2 : g_stat1;
    const float* row  = part + (size_t)blockIdx.x * NB_CONV;
    float s = 0.f;
#pragma unroll 4
    for (int i = threadIdx.x; i < NB_CONV; i += 256) s += row[i];
    __shared__ float sh[256];
    sh[threadIdx.x] = s;
    __syncthreads();
#pragma unroll
    for (int o = 128; o > 0; o >>= 1) {
        if (threadIdx.x < o) sh[threadIdx.x] += sh[threadIdx.x + o];
        __syncthreads();
    }
    if (threadIdx.x == 0) stat[blockIdx.x] = sh[0];
}

__global__ void coef_kernel(const float* __restrict__ gamma,
                            const float* __restrict__ beta, int which)
{
    const float* stat = which ? g_stat2 : g_stat1;
    float*       coef = which ? g_coef2 : g_coef1;
    int c = threadIdx.x;
    float mean = stat[c] / (float)N_ACT;
    float var  = fmaxf(stat[32 + c] / (float)N_ACT - mean * mean, 0.f);
    float a    = gamma[c] * rsqrtf(var + BN_EPS);
    coef[c]      = a;
    coef[32 + c] = beta[c] - mean * a;
}

// ---------------- bn2 + residual add -> out (h2 read as fp16) ----------------
__global__ void final_kernel(const float* __restrict__ X, float* __restrict__ O)
{
    int i4 = blockIdx.x * 256 + threadIdx.x;
    int cb = i4 & 7;
    float4 a = ((const float4*)g_coef2)[cb];
    float4 c = ((const float4*)g_coef2)[8 + cb];
    uint2 hv = ((const uint2*)g_h2h)[i4];
    float2 v01 = __half22float2(*(__half2*)&hv.x);
    float2 v23 = __half22float2(*(__half2*)&hv.y);
    float4 x = ((const float4*)X)[i4];
    float4 o;
    o.x = fmaf(v01.x, a.x, c.x) + x.x;
    o.y = fmaf(v01.y, a.y, c.y) + x.y;
    o.z = fmaf(v23.x, a.z, c.z) + x.z;
    o.w = fmaf(v23.y, a.w, c.w) + x.w;
    ((float4*)O)[i4] = o;
}

extern "C" void kernel_launch(void* const* d_in, const int* in_sizes, int n_in,
                              void* d_out, int out_size)
{
    const float* x   = (const float*)d_in[0];
    const int*   idx = (const int*)  d_in[1];
    const float* W1  = (const float*)d_in[2];
    const float* g1  = (const float*)d_in[3];
    const float* b1  = (const float*)d_in[4];
    const float* W2  = (const float*)d_in[5];
    const float* g2  = (const float*)d_in[6];
    const float* b2  = (const float*)d_in[7];
    float* out = (float*)d_out;

    prep_w<<<8, 256>>>(W1, 0);
    prep_w<<<8, 256>>>(W2, 1);
    conv_mma<0><<<NB_CONV, 256>>>(x, idx);    // h1 = conv1(x) (fp16), partials1
    reduce_kernel<<<64, 256>>>(0);
    coef_kernel  <<<1, 32>>>(g1, b1, 0);
    conv_mma<1><<<NB_CONV, 256>>>(x, idx);    // h2 = conv2(bn1relu(h1)) (fp16)
    reduce_kernel<<<64, 256>>>(1);
    coef_kernel  <<<1, 32>>>(g2, b2, 1);
    final_kernel <<<NB_ELT, 256>>>(x, out);   // out = bn2(h2) + x
}